// round 11
// baseline (speedup 1.0000x reference)
#include <cuda_runtime.h>
#include <cuda_bf16.h>
#include <math.h>
#include <stdint.h>

// Problem constants
#define T_STEPS 256
#define Bsz     512
#define Hh      512
#define NQv     8
#define NTOT    2056
#define NP      2176          // padded to 17*128
#define KV      1536          // virtual K: [hi@hi | hi@lo | lo@hi]
#define ALPHA_C 0.7f
#define NBLK    148           // persistent grid (== SM count)
#define GTILES  136           // 17 n-tiles x 8 m-tiles

// Scratch (no cudaMalloc allowed)
__device__ __align__(16) __nv_bfloat16 g_BX[KV * NP];
__device__ __align__(16) __nv_bfloat16 g_BH[KV * NP];
__device__ __align__(16) __nv_bfloat16 g_Xhi[(size_t)T_STEPS * Bsz * 512];
__device__ __align__(16) __nv_bfloat16 g_Xlo[(size_t)T_STEPS * Bsz * 512];
__device__ __align__(16) float g_ball[NP];
__device__ __align__(16) float g_preX[(size_t)T_STEPS * Bsz * NP];
__device__ __align__(16) float g_pre[Bsz * NP];
__device__ __align__(16) __nv_bfloat16 g_hxhi[Bsz * Hh];
__device__ __align__(16) __nv_bfloat16 g_hxlo[Bsz * Hh];
__device__ __align__(16) float g_hx[Bsz * Hh];
__device__ __align__(16) float g_cx[Bsz * Hh];
__device__ unsigned g_cnt;
__device__ unsigned g_gen;

__device__ __forceinline__ float sig_fast(float x) {
    return __fdividef(1.0f, 1.0f + __expf(-x));
}
__device__ __forceinline__ float tanh_fast(float x) {
    x = fminf(fmaxf(x, -15.0f), 15.0f);
    float e = __expf(2.0f * x);
    return (e - 1.0f) * __fdividef(1.0f, e + 1.0f);
}

__device__ __forceinline__ void cp16(uint32_t dst, const void* src) {
    asm volatile("cp.async.cg.shared.global [%0], [%1], 16;\n" :: "r"(dst), "l"(src));
}

// ---------------------------------------------------------------------------
// Pack weights into split-bf16 B matrices; init state + barrier counters.
// ---------------------------------------------------------------------------
__global__ void pack_kernel(const float* __restrict__ Wf, const float* __restrict__ Wi,
                            const float* __restrict__ Wu, const float* __restrict__ Wo,
                            const float* __restrict__ Wq,
                            const float* __restrict__ bf, const float* __restrict__ bi,
                            const float* __restrict__ bu, const float* __restrict__ bo,
                            const float* __restrict__ bq) {
    int stride = gridDim.x * blockDim.x;
    int idx = blockIdx.x * blockDim.x + threadIdx.x;

    if (idx == 0) { g_cnt = 0; g_gen = 0; }

    for (size_t e = idx; e < (size_t)KV * NP; e += stride) {
        int kv = (int)(e / NP), n = (int)(e - (size_t)kv * NP);
        int r = kv & 511;
        int region = kv >> 9;      // 0:hi 1:lo 2:hi
        float wx = 0.0f, wh = 0.0f;
        if (n < 2048) {
            int g = n >> 9, c = n & 511;
            const float* W = (g == 0) ? Wf : (g == 1) ? Wi : (g == 2) ? Wu : Wo;
            wx = W[r * 512 + c];
            wh = W[(512 + r) * 512 + c];
        } else if (n < NTOT) {
            wx = Wq[r * NQv + (n - 2048)];
            wh = Wq[(512 + r) * NQv + (n - 2048)];
        }
        __nv_bfloat16 xh = __float2bfloat16_rn(wx);
        __nv_bfloat16 hh = __float2bfloat16_rn(wh);
        if (region == 1) {
            g_BX[e] = __float2bfloat16_rn(wx - __bfloat162float(xh));
            g_BH[e] = __float2bfloat16_rn(wh - __bfloat162float(hh));
        } else {
            g_BX[e] = xh;
            g_BH[e] = hh;
        }
    }
    for (int n = idx; n < NP; n += stride) {
        float v = 0.0f;
        if (n < 2048) {
            int g = n >> 9, c = n & 511;
            const float* bb = (g == 0) ? bf : (g == 1) ? bi : (g == 2) ? bu : bo;
            v = bb[c];
        } else if (n < NTOT) {
            v = bq[n - 2048];
        }
        g_ball[n] = v;
    }
    for (int e = idx; e < Bsz * Hh; e += stride) {
        g_hx[e] = 0.0f;
        g_cx[e] = 0.0f;
        g_hxhi[e] = __float2bfloat16_rn(0.0f);
        g_hxlo[e] = __float2bfloat16_rn(0.0f);
    }
}

// ---------------------------------------------------------------------------
// Split inputs into bf16 hi/lo.
// ---------------------------------------------------------------------------
__global__ void convert_x(const float* __restrict__ inputs) {
    size_t N = (size_t)T_STEPS * Bsz * 512;
    size_t stride = (size_t)gridDim.x * blockDim.x;
    for (size_t i = (size_t)blockIdx.x * blockDim.x + threadIdx.x; i < N; i += stride) {
        float v = inputs[i];
        __nv_bfloat16 h = __float2bfloat16_rn(v);
        g_Xhi[i] = h;
        g_Xlo[i] = __float2bfloat16_rn(v - __bfloat162float(h));
    }
}

// ---------------------------------------------------------------------------
// Big GEMM (x-part, all timesteps): 128x128 tile, register prefetch.
// ---------------------------------------------------------------------------
__global__ __launch_bounds__(256) void bgemm_big() {
    __shared__ __align__(16) __nv_bfloat16 As[128][40];
    __shared__ __align__(16) __nv_bfloat16 Bs[32][136];

    const int tid  = threadIdx.x;
    const int lane = tid & 31;
    const int wid  = tid >> 5;
    const int m0   = blockIdx.y * 128;
    const int n0   = blockIdx.x * 128;

    const int arow = tid >> 2, aseg = (tid & 3) << 3;
    const int brow = tid >> 4, bseg = (tid & 15) << 3;
    const int wm = wid % 4, wn = wid / 4;   // WTN=64, NT_N=8

    const uint32_t As_base = (uint32_t)__cvta_generic_to_shared(&As[0][0]);
    const uint32_t Bs_base = (uint32_t)__cvta_generic_to_shared(&Bs[0][0]);
    const int a_r  = wm * 32 + (lane & 15);
    const int a_c  = (lane >> 4) << 3;
    const int b_r  = (lane & 15);
    const int b_c0 = wn * 64 + ((lane >> 4) << 3);

    float acc[2][8][4];
#pragma unroll
    for (int i = 0; i < 2; ++i)
#pragma unroll
        for (int j = 0; j < 8; ++j)
#pragma unroll
            for (int k = 0; k < 4; ++k) acc[i][j][k] = 0.0f;

    uint4 apre[2], bpre[2];
#pragma unroll
    for (int p = 0; p < 2; ++p)
        apre[p] = *(const uint4*)(g_Xhi + (size_t)(m0 + arow + p * 64) * 512 + aseg);
#pragma unroll
    for (int p = 0; p < 2; ++p)
        bpre[p] = *(const uint4*)(g_BX + (size_t)(brow + p * 16) * NP + n0 + bseg);

    const int nIter = KV / 32;
    for (int it = 0; it < nIter; ++it) {
#pragma unroll
        for (int p = 0; p < 2; ++p)
            *(uint4*)(&As[arow + p * 64][aseg]) = apre[p];
        *(uint4*)(&Bs[brow][bseg])      = bpre[0];
        *(uint4*)(&Bs[brow + 16][bseg]) = bpre[1];
        __syncthreads();

        if (it + 1 < nIter) {
            int kv = (it + 1) * 32;
            int acol = kv & 511;
            const __nv_bfloat16* Ablk = (kv >= 1024) ? g_Xlo : g_Xhi;
#pragma unroll
            for (int p = 0; p < 2; ++p)
                apre[p] = *(const uint4*)(Ablk + (size_t)(m0 + arow + p * 64) * 512 + acol + aseg);
#pragma unroll
            for (int p = 0; p < 2; ++p)
                bpre[p] = *(const uint4*)(g_BX + (size_t)(kv + brow + p * 16) * NP + n0 + bseg);
        }

#pragma unroll
        for (int kp = 0; kp < 2; ++kp) {
            uint32_t a[2][4];
#pragma unroll
            for (int mt = 0; mt < 2; ++mt) {
                uint32_t addr = As_base + (uint32_t)(((a_r + mt * 16) * 40 + a_c + kp * 16) * 2);
                asm volatile("ldmatrix.sync.aligned.m8n8.x4.shared.b16 {%0,%1,%2,%3}, [%4];"
                             : "=r"(a[mt][0]), "=r"(a[mt][1]), "=r"(a[mt][2]), "=r"(a[mt][3])
                             : "r"(addr));
            }
            uint32_t b[8][2];
#pragma unroll
            for (int npair = 0; npair < 4; ++npair) {
                uint32_t addr = Bs_base + (uint32_t)(((b_r + kp * 16) * 136 + b_c0 + npair * 16) * 2);
                asm volatile("ldmatrix.sync.aligned.m8n8.x4.trans.shared.b16 {%0,%1,%2,%3}, [%4];"
                             : "=r"(b[2 * npair][0]), "=r"(b[2 * npair][1]),
                               "=r"(b[2 * npair + 1][0]), "=r"(b[2 * npair + 1][1])
                             : "r"(addr));
            }
#pragma unroll
            for (int mt = 0; mt < 2; ++mt)
#pragma unroll
                for (int nt = 0; nt < 8; ++nt) {
                    asm volatile(
                        "mma.sync.aligned.m16n8k16.row.col.f32.bf16.bf16.f32 "
                        "{%0,%1,%2,%3}, {%4,%5,%6,%7}, {%8,%9}, {%0,%1,%2,%3};"
                        : "+f"(acc[mt][nt][0]), "+f"(acc[mt][nt][1]),
                          "+f"(acc[mt][nt][2]), "+f"(acc[mt][nt][3])
                        : "r"(a[mt][0]), "r"(a[mt][1]), "r"(a[mt][2]), "r"(a[mt][3]),
                          "r"(b[nt][0]), "r"(b[nt][1]));
                }
        }
        __syncthreads();
    }

#pragma unroll
    for (int mt = 0; mt < 2; ++mt) {
        int r0 = m0 + wm * 32 + mt * 16 + (lane >> 2);
#pragma unroll
        for (int nt = 0; nt < 8; ++nt) {
            int c = n0 + wn * 64 + nt * 8 + (lane & 3) * 2;
            float b0 = g_ball[c], b1 = g_ball[c + 1];
            *(float2*)(g_preX + (size_t)r0 * NP + c) =
                make_float2(acc[mt][nt][0] + b0, acc[mt][nt][1] + b1);
            *(float2*)(g_preX + (size_t)(r0 + 8) * NP + c) =
                make_float2(acc[mt][nt][2] + b0, acc[mt][nt][3] + b1);
        }
    }
}

// ---------------------------------------------------------------------------
// Grid-wide barrier (all NBLK blocks resident; generation + counter).
// ---------------------------------------------------------------------------
__device__ __forceinline__ void grid_sync() {
    __syncthreads();
    if (threadIdx.x == 0) {
        unsigned g = *((volatile unsigned*)&g_gen);
        __threadfence();
        if (atomicAdd(&g_cnt, 1u) == NBLK - 1) {
            g_cnt = 0;
            __threadfence();
            atomicAdd(&g_gen, 1u);
        } else {
            while (*((volatile unsigned*)&g_gen) == g) { }
        }
        __threadfence();
    }
    __syncthreads();
}

// ---------------------------------------------------------------------------
// Persistent recurrence kernel: for each t, (1) 64x128-tile split-bf16 MMA
// GEMM of hx @ Wh into g_pre with a 3-stage cp.async pipeline, (2) grid sync,
// (3) distributed pointwise gate/quantum/LSTM update, (4) grid sync.
// ---------------------------------------------------------------------------
__global__ __launch_bounds__(256, 1) void qlstm_persist(
    const float* __restrict__ Wqh, const float* __restrict__ bqh,
    const float* __restrict__ th_f, const float* __restrict__ th_i,
    const float* __restrict__ th_u, const float* __restrict__ th_o,
    float* __restrict__ out)
{
    __shared__ __align__(16) __nv_bfloat16 As[3][64][40];    // 3 x 5120 B
    __shared__ __align__(16) __nv_bfloat16 Bs[3][32][136];   // 3 x 8704 B
    __shared__ float qv[4][NQv];

    const int tid  = threadIdx.x;
    const int lane = tid & 31;
    const int wid  = tid >> 5;
    const bool doGemm = (blockIdx.x < GTILES);
    const int bx = blockIdx.x % 17, by = blockIdx.x / 17;
    const int n0 = bx * 128, m0 = by * 64;

    // warp tiling for BM=64: WM=2, WN=4, WTN=32, NT_N=4
    const int wm = wid & 1, wn = wid >> 1;
    const uint32_t As_u = (uint32_t)__cvta_generic_to_shared(&As[0][0][0]);
    const uint32_t Bs_u = (uint32_t)__cvta_generic_to_shared(&Bs[0][0][0]);
    const int a_r  = wm * 32 + (lane & 15);
    const int a_c  = (lane >> 4) << 3;
    const int b_r  = lane & 15;
    const int b_c0 = wn * 32 + ((lane >> 4) << 3);
    const int arow = tid >> 2, aseg = (tid & 3) << 3;
    const int brow = tid >> 4, bseg = (tid & 15) << 3;

    for (int t = 0; t < T_STEPS; ++t) {
        // ---------------- GEMM phase ----------------
        if (doGemm) {
            float acc[2][4][4];
#pragma unroll
            for (int i = 0; i < 2; ++i)
#pragma unroll
                for (int j = 0; j < 4; ++j)
#pragma unroll
                    for (int k = 0; k < 4; ++k) acc[i][j][k] = 0.0f;

            // prologue: stages 0,1 (kv = 0, 32 -> both in hi region)
#pragma unroll
            for (int s = 0; s < 2; ++s) {
                int kv = s * 32;
                cp16(As_u + s * 5120 + (arow * 40 + aseg) * 2,
                     g_hxhi + (size_t)(m0 + arow) * 512 + kv + aseg);
                cp16(Bs_u + s * 8704 + (brow * 136 + bseg) * 2,
                     g_BH + (size_t)(kv + brow) * NP + n0 + bseg);
                cp16(Bs_u + s * 8704 + ((brow + 16) * 136 + bseg) * 2,
                     g_BH + (size_t)(kv + brow + 16) * NP + n0 + bseg);
                asm volatile("cp.async.commit_group;\n");
            }

            for (int it = 0; it < 48; ++it) {
                asm volatile("cp.async.wait_group 1;\n");
                __syncthreads();

                if (it + 2 < 48) {
                    int kv = (it + 2) * 32;
                    int slot = (it + 2) % 3;
                    int acol = kv & 511;
                    const __nv_bfloat16* Ablk = (kv >= 1024) ? g_hxlo : g_hxhi;
                    cp16(As_u + slot * 5120 + (arow * 40 + aseg) * 2,
                         Ablk + (size_t)(m0 + arow) * 512 + acol + aseg);
                    cp16(Bs_u + slot * 8704 + (brow * 136 + bseg) * 2,
                         g_BH + (size_t)(kv + brow) * NP + n0 + bseg);
                    cp16(Bs_u + slot * 8704 + ((brow + 16) * 136 + bseg) * 2,
                         g_BH + (size_t)(kv + brow + 16) * NP + n0 + bseg);
                }
                asm volatile("cp.async.commit_group;\n");

                const int st = it % 3;
                const uint32_t asb = As_u + st * 5120;
                const uint32_t bsb = Bs_u + st * 8704;
#pragma unroll
                for (int kp = 0; kp < 2; ++kp) {
                    uint32_t a[2][4];
#pragma unroll
                    for (int mt = 0; mt < 2; ++mt) {
                        uint32_t addr = asb + (uint32_t)(((a_r + mt * 16) * 40 + a_c + kp * 16) * 2);
                        asm volatile("ldmatrix.sync.aligned.m8n8.x4.shared.b16 {%0,%1,%2,%3}, [%4];"
                                     : "=r"(a[mt][0]), "=r"(a[mt][1]), "=r"(a[mt][2]), "=r"(a[mt][3])
                                     : "r"(addr));
                    }
                    uint32_t b[4][2];
#pragma unroll
                    for (int npair = 0; npair < 2; ++npair) {
                        uint32_t addr = bsb + (uint32_t)(((b_r + kp * 16) * 136 + b_c0 + npair * 16) * 2);
                        asm volatile("ldmatrix.sync.aligned.m8n8.x4.trans.shared.b16 {%0,%1,%2,%3}, [%4];"
                                     : "=r"(b[2 * npair][0]), "=r"(b[2 * npair][1]),
                                       "=r"(b[2 * npair + 1][0]), "=r"(b[2 * npair + 1][1])
                                     : "r"(addr));
                    }
#pragma unroll
                    for (int mt = 0; mt < 2; ++mt)
#pragma unroll
                        for (int nt = 0; nt < 4; ++nt) {
                            asm volatile(
                                "mma.sync.aligned.m16n8k16.row.col.f32.bf16.bf16.f32 "
                                "{%0,%1,%2,%3}, {%4,%5,%6,%7}, {%8,%9}, {%0,%1,%2,%3};"
                                : "+f"(acc[mt][nt][0]), "+f"(acc[mt][nt][1]),
                                  "+f"(acc[mt][nt][2]), "+f"(acc[mt][nt][3])
                                : "r"(a[mt][0]), "r"(a[mt][1]), "r"(a[mt][2]), "r"(a[mt][3]),
                                  "r"(b[nt][0]), "r"(b[nt][1]));
                        }
                }
            }

            // epilogue -> g_pre
#pragma unroll
            for (int mt = 0; mt < 2; ++mt) {
                int r0 = m0 + wm * 32 + mt * 16 + (lane >> 2);
#pragma unroll
                for (int nt = 0; nt < 4; ++nt) {
                    int c = n0 + wn * 32 + nt * 8 + (lane & 3) * 2;
                    *(float2*)(g_pre + (size_t)r0 * NP + c) =
                        make_float2(acc[mt][nt][0], acc[mt][nt][1]);
                    *(float2*)(g_pre + (size_t)(r0 + 8) * NP + c) =
                        make_float2(acc[mt][nt][2], acc[mt][nt][3]);
                }
            }
        }

        grid_sync();

        // ---------------- pointwise phase ----------------
        for (int b = blockIdx.x; b < Bsz; b += NBLK) {
            const float* px = g_preX + ((size_t)t * Bsz + b) * NP;
            const float* pr = g_pre + (size_t)b * NP;

            __syncthreads();
            if (tid < 4) {
                const float* th = (tid == 0) ? th_f : (tid == 1) ? th_i
                                 : (tid == 2) ? th_u : th_o;
                float p = 1.0f;
#pragma unroll
                for (int w = 0; w < NQv; ++w) {
                    float q = px[2048 + w] + pr[2048 + w];
                    p *= cosf(q + th[w]);
                    qv[tid][w] = p;
                }
            }
            __syncthreads();

#pragma unroll
            for (int hh = 0; hh < 2; ++hh) {
                int h = tid + hh * 256;
                float zf = bqh[h];
                float zi = zf, zu = zf, zo = zf;
#pragma unroll
                for (int w = 0; w < NQv; ++w) {
                    float wq = Wqh[w * Hh + h];
                    zf = fmaf(qv[0][w], wq, zf);
                    zi = fmaf(qv[1][w], wq, zi);
                    zu = fmaf(qv[2][w], wq, zu);
                    zo = fmaf(qv[3][w], wq, zo);
                }

                float pf = px[h]        + pr[h];
                float pi = px[512 + h]  + pr[512 + h];
                float pu = px[1024 + h] + pr[1024 + h];
                float po = px[1536 + h] + pr[1536 + h];

                const float A1 = 1.0f - ALPHA_C;
                float f  = ALPHA_C * sig_fast(pf)  + A1 * sig_fast(zf);
                float ii = ALPHA_C * sig_fast(pi)  + A1 * sig_fast(zi);
                float g  = ALPHA_C * tanh_fast(pu) + A1 * tanh_fast(zu);
                float o  = ALPHA_C * sig_fast(po)  + A1 * sig_fast(zo);

                size_t idx = (size_t)b * Hh + h;
                float c  = f * g_cx[idx] + ii * g;
                float hv = o * tanh_fast(c);
                g_cx[idx] = c;
                g_hx[idx] = hv;

                __nv_bfloat16 hb = __float2bfloat16_rn(hv);
                g_hxhi[idx] = hb;
                g_hxlo[idx] = __float2bfloat16_rn(hv - __bfloat162float(hb));

                out[(size_t)t * (Bsz * Hh) + idx] = hv;
            }
        }

        grid_sync();
    }
}

// ---------------------------------------------------------------------------
// Append final (hx, cx) after out[T,B,H].
// ---------------------------------------------------------------------------
__global__ void final_copy(float* __restrict__ dst) {
    int i = blockIdx.x * blockDim.x + threadIdx.x;
    if (i < Bsz * Hh) {
        dst[i] = g_hx[i];
        dst[Bsz * Hh + i] = g_cx[i];
    }
}

extern "C" void kernel_launch(void* const* d_in, const int* in_sizes, int n_in,
                              void* d_out, int out_size) {
    (void)in_sizes; (void)n_in; (void)out_size;
    const float* inputs = (const float*)d_in[0];
    const float* Wf  = (const float*)d_in[1];
    const float* bf  = (const float*)d_in[2];
    const float* Wi  = (const float*)d_in[3];
    const float* bi  = (const float*)d_in[4];
    const float* Wu  = (const float*)d_in[5];
    const float* bu  = (const float*)d_in[6];
    const float* Wo  = (const float*)d_in[7];
    const float* bo  = (const float*)d_in[8];
    const float* Wq  = (const float*)d_in[9];
    const float* bq  = (const float*)d_in[10];
    const float* Wqh = (const float*)d_in[11];
    const float* bqh = (const float*)d_in[12];
    const float* th_f = (const float*)d_in[13];
    const float* th_i = (const float*)d_in[14];
    const float* th_u = (const float*)d_in[15];
    const float* th_o = (const float*)d_in[16];
    float* out = (float*)d_out;

    pack_kernel<<<512, 256>>>(Wf, Wi, Wu, Wo, Wq, bf, bi, bu, bo, bq);
    convert_x<<<4096, 256>>>(inputs);

    // Big x-part GEMM: M = 131072, virtual K = 1536, N = NP
    dim3 bigGrid(NP / 128, (T_STEPS * Bsz) / 128);
    bgemm_big<<<bigGrid, 256>>>();

    // Persistent recurrence: all 256 steps in one launch
    qlstm_persist<<<NBLK, 256>>>(Wqh, bqh, th_f, th_i, th_u, th_o, out);

    final_copy<<<(Bsz * Hh + 255) / 256, 256>>>(out + (size_t)T_STEPS * Bsz * Hh);
}